// round 2
// baseline (speedup 1.0000x reference)
#include <cuda_runtime.h>

#define FOV_TAN 0.57735026918962576451f   // tan(30 deg)
#define HALF    1.494140625f              // 255 * (3/256) * 0.5
#define NC      5                         // depth chunks
#define CSTEP   64                        // 320 / NC
#define NPIX    65536

// ---- scratch (static device arrays; no allocations allowed) ----
__device__ float g_cRGB[NC * NPIX];
__device__ float g_cT[NC * NPIX];
__device__ float g_gray[NPIX];
__device__ float g_psum[256], g_psq[256], g_pmin[256], g_pmax[256];
__device__ float g_scal[4];          // mean, sigma+eps, stdmin, denom
__device__ unsigned g_cnt = 0;       // self-resetting last-block counter

// ===========================================================================
// Kernel 1: ray-march one depth chunk per block over a 32x8 pixel tile.
// warp = 32 consecutive w (coalesced in volume W); 8 rows/block share y rows
// in L1. grid = (8 wtiles, 32 htiles, NC chunks), block = 256.
// ===========================================================================
__global__ __launch_bounds__(256) void render_k(
    const float* __restrict__ vol,
    const float* __restrict__ camR,
    const float* __restrict__ camT)
{
    const int t = threadIdx.x;
    const int w = (blockIdx.x << 5) + (t & 31);
    const int h = (blockIdx.y << 3) + (t >> 5);
    const int c = blockIdx.z;

    // linspace(-1, 1, 256)
    const float gx = __fadd_rn(-1.0f, __fmul_rn((float)w, 2.0f / 255.0f));
    const float gy = __fadd_rn(-1.0f, __fmul_rn((float)h, 2.0f / 255.0f));
    const float dcx = __fmul_rn(gx, FOV_TAN);
    const float dcy = __fmul_rn(gy, FOV_TAN);

    const float R0 = camR[0], R1 = camR[1], R2 = camR[2];
    const float R3 = camR[3], R4 = camR[4], R5 = camR[5];
    const float R6 = camR[6], R7 = camR[7], R8 = camR[8];
    const float T0 = camT[0], T1 = camT[1], T2 = camT[2];

    // origin = -R^T T ;  dir = R^T dirs_cam   (Rt[i][j] = R[j][i])
    const float ox = -(R0 * T0 + R3 * T1 + R6 * T2);
    const float oy = -(R1 * T0 + R4 * T1 + R7 * T2);
    const float oz = -(R2 * T0 + R5 * T1 + R8 * T2);
    const float dx = R0 * dcx + R3 * dcy + R6;
    const float dy = R1 * dcx + R4 * dcy + R7;
    const float dz = R2 * dcx + R5 * dcy + R8;

    float Tr  = 1.0f;
    float acc = 0.0f;
    const int p0 = c * CSTEP;

    #pragma unroll 4
    for (int i = 0; i < CSTEP; i++) {
        const int p = p0 + i;
        // linspace(2, 6, 320)
        const float d = __fadd_rn(2.0f, __fmul_rn((float)p, 4.0f / 319.0f));
        // local coords, op-order mirroring the reference (unfused)
        const float lx = __fdiv_rn(__fadd_rn(ox, __fmul_rn(dx, d)), HALF);
        const float ly = __fdiv_rn(__fadd_rn(oy, __fmul_rn(dy, d)), HALF);
        const float lz = __fdiv_rn(__fadd_rn(oz, __fmul_rn(dz, d)), HALF);

        const bool inside = (fabsf(lx) <= 1.0f) & (fabsf(ly) <= 1.0f) & (fabsf(lz) <= 1.0f);
        if (inside) {
            const float fx = __fmul_rn(__fmul_rn(__fadd_rn(lx, 1.0f), 0.5f), 255.0f);
            const float fy = __fmul_rn(__fmul_rn(__fadd_rn(ly, 1.0f), 0.5f), 255.0f);
            const float fz = __fmul_rn(__fmul_rn(__fadd_rn(lz, 1.0f), 0.5f), 255.0f);

            const float xf = floorf(fx), yf = floorf(fy), zf = floorf(fz);
            const float wx = fx - xf, wy = fy - yf, wz = fz - zf;
            const int x0 = (int)xf, y0 = (int)yf, z0 = (int)zf;  // in [0,255] when inside
            const int x1 = min(x0 + 1, 255);
            const int y1 = min(y0 + 1, 255);
            const int z1 = min(z0 + 1, 255);

            const float* b00 = vol + ((((z0 << 8) + y0) << 8));
            const float* b01 = vol + ((((z0 << 8) + y1) << 8));
            const float* b10 = vol + ((((z1 << 8) + y0) << 8));
            const float* b11 = vol + ((((z1 << 8) + y1) << 8));

            const float v000 = __ldg(b00 + x0), v001 = __ldg(b00 + x1);
            const float v010 = __ldg(b01 + x0), v011 = __ldg(b01 + x1);
            const float v100 = __ldg(b10 + x0), v101 = __ldg(b10 + x1);
            const float v110 = __ldg(b11 + x0), v111 = __ldg(b11 + x1);

            const float c00 = fmaf(wx, v001 - v000, v000);
            const float c01 = fmaf(wx, v011 - v010, v010);
            const float c10 = fmaf(wx, v101 - v100, v100);
            const float c11 = fmaf(wx, v111 - v110, v110);
            const float c0  = fmaf(wy, c01 - c00, c00);
            const float c1  = fmaf(wy, c11 - c10, c10);
            const float s   = fmaf(wz, c1 - c0, c0);

            // alpha = 0.1 exactly (constant density); 1-0.1+1e-10 -> 0.9f in fp32
            acc = fmaf(0.1f * Tr, s, acc);
            Tr *= 0.9f;
        }
        // outside: one_m = 1 + 1e-10 -> 1.0f in fp32: T unchanged
    }

    const int pix = (h << 8) + w;
    g_cRGB[c * NPIX + pix] = acc;
    g_cT[c * NPIX + pix]   = Tr;
}

// ===========================================================================
// Kernel 2: combine chunks front-to-back, store gray, per-block partials,
// and have the LAST block (self-resetting counter) do the deterministic
// final reduction + scalar computation.
// ===========================================================================
__global__ __launch_bounds__(256) void combine_k()
{
    const int t   = threadIdx.x;
    const int pix = (blockIdx.x << 8) + t;

    float T = 1.0f, G = 0.0f;
    #pragma unroll
    for (int c = 0; c < NC; c++) {
        G = fmaf(T, g_cRGB[c * NPIX + pix], G);
        T *= g_cT[c * NPIX + pix];
    }
    g_gray[pix] = G;

    __shared__ float ssum[256], ssq[256], smin[256], smax[256];
    ssum[t] = G; ssq[t] = G * G; smin[t] = G; smax[t] = G;
    for (int o = 128; o > 0; o >>= 1) {
        __syncthreads();
        if (t < o) {
            ssum[t] += ssum[t + o];
            ssq[t]  += ssq[t + o];
            smin[t]  = fminf(smin[t], smin[t + o]);
            smax[t]  = fmaxf(smax[t], smax[t + o]);
        }
    }

    __shared__ bool last;
    if (t == 0) {
        g_psum[blockIdx.x] = ssum[0];
        g_psq[blockIdx.x]  = ssq[0];
        g_pmin[blockIdx.x] = smin[0];
        g_pmax[blockIdx.x] = smax[0];
        __threadfence();
        // atomicInc wraps to 0 after the 256th arrival -> self-resetting,
        // safe under CUDA-graph replay.
        last = (atomicInc(&g_cnt, 255u) == 255u);
    }
    __syncthreads();
    if (!last) return;

    // ---- final deterministic reduction over the 256 partials ----
    __shared__ double dsum[256], dsq[256];
    __shared__ float  fmn[256], fmx[256];
    dsum[t] = (double)g_psum[t];
    dsq[t]  = (double)g_psq[t];
    fmn[t]  = g_pmin[t];
    fmx[t]  = g_pmax[t];
    for (int o = 128; o > 0; o >>= 1) {
        __syncthreads();
        if (t < o) {
            dsum[t] += dsum[t + o];
            dsq[t]  += dsq[t + o];
            fmn[t]   = fminf(fmn[t], fmn[t + o]);
            fmx[t]   = fmaxf(fmx[t], fmx[t + o]);
        }
    }
    if (t == 0) {
        const double N = (double)NPIX;
        const double sum = dsum[0], sq = dsq[0];
        const double mean = sum / N;
        double var = (sq - sum * sum / N) / (N - 1.0);
        if (var < 0.0) var = 0.0;
        const float meanf = (float)mean;
        const float s     = (float)sqrt(var) + 1e-8f;     // sigma(ddof=1) + EPS
        const float stdmn = (fmn[0] - meanf) / s;
        const float stdmx = (fmx[0] - meanf) / s;
        g_scal[0] = meanf;
        g_scal[1] = s;
        g_scal[2] = stdmn;
        g_scal[3] = stdmx - stdmn + 1e-8f;                // denom
    }
}

// ===========================================================================
// Kernel 3: normalize + transpose, both sides coalesced via 32x32 smem tile.
// out[w*256 + h] = ((g[h*256+w]-mean)/s - stdmin + EPS) / denom
// grid = (8, 8) tiles, block = (32, 8).
// ===========================================================================
__global__ __launch_bounds__(256) void norm_k(float* __restrict__ out)
{
    __shared__ float tile[32][33];
    const int tx = threadIdx.x;          // 0..31
    const int ty = threadIdx.y;          // 0..7
    const int wbase = blockIdx.x << 5;
    const int hbase = blockIdx.y << 5;

    #pragma unroll
    for (int j = 0; j < 32; j += 8) {
        const int h = hbase + ty + j;
        tile[ty + j][tx] = g_gray[(h << 8) + wbase + tx];   // coalesced read (w contiguous)
    }
    __syncthreads();

    const float mean  = g_scal[0];
    const float s     = g_scal[1];
    const float stdmn = g_scal[2];
    const float denom = g_scal[3];

    #pragma unroll
    for (int j = 0; j < 32; j += 8) {
        const int w = wbase + ty + j;
        const float g = tile[tx][ty + j];
        const float stdv = (g - mean) / s;
        out[(w << 8) + hbase + tx] = (stdv - stdmn + 1e-8f) / denom;  // coalesced write (h contiguous)
    }
}

extern "C" void kernel_launch(void* const* d_in, const int* in_sizes, int n_in,
                              void* d_out, int out_size)
{
    const float* vol  = (const float*)d_in[0];   // image3d (1,1,256,256,256)
    const float* camR = (const float*)d_in[1];   // (1,3,3)
    const float* camT = (const float*)d_in[2];   // (1,3)
    float* out = (float*)d_out;                  // (1,1,256,256)

    render_k<<<dim3(8, 32, NC), 256>>>(vol, camR, camT);
    combine_k<<<256, 256>>>();
    norm_k<<<dim3(8, 8), dim3(32, 8)>>>(out);
}

// round 3
// speedup vs baseline: 1.8410x; 1.8410x over previous
#include <cuda_runtime.h>

#define FOV_TAN 0.57735026918962576451f   // tan(30 deg)
#define HALF    1.494140625f              // 255 * (3/256) * 0.5
#define NC      5                         // depth chunks
#define CSTEP   64                        // 320 / NC
#define NPIX    65536
#define DSTEP   (4.0f / 319.0f)           // linspace(2,6,320) step

// ---- scratch (static device arrays; no allocations allowed) ----
__device__ float g_cRGB[NC * NPIX];
__device__ float g_cT[NC * NPIX];
__device__ float g_gray[NPIX];
__device__ float g_psum[256], g_psq[256], g_pmin[256], g_pmax[256];
__device__ float g_scal[4];          // mean, sigma+eps, stdmin, denom
__device__ unsigned g_cnt = 0;       // self-resetting last-block counter

// Intersect fx(p) = c0 + s*p with [0, 255]; accumulate into [tlo, thi].
__device__ __forceinline__ void axis_bounds(float c0, float s, float& tlo, float& thi)
{
    if (s > 0.0f) {
        tlo = fmaxf(tlo, (0.0f   - c0) / s);
        thi = fminf(thi, (255.0f - c0) / s);
    } else if (s < 0.0f) {
        tlo = fmaxf(tlo, (255.0f - c0) / s);
        thi = fminf(thi, (0.0f   - c0) / s);
    } else if (c0 < 0.0f || c0 > 255.0f) {
        tlo = 1e30f; thi = -1e30f;
    }
}

// ===========================================================================
// Kernel 1: ray-march one depth chunk per block. block = one image row
// (256 w), grid = (256 h, NC chunks).  Voxel coords are affine in the step
// index p:  f(p) = c0 + p*s  -> 3 FMAs/step, no divisions in the loop.
// ===========================================================================
__global__ __launch_bounds__(256) void render_k(
    const float* __restrict__ vol,
    const float* __restrict__ camR,
    const float* __restrict__ camT)
{
    const int w = threadIdx.x;
    const int h = blockIdx.x;
    const int c = blockIdx.y;

    // linspace(-1, 1, 256)
    const float gx = fmaf((float)w, 2.0f / 255.0f, -1.0f);
    const float gy = fmaf((float)h, 2.0f / 255.0f, -1.0f);
    const float dcx = gx * FOV_TAN;
    const float dcy = gy * FOV_TAN;

    const float R0 = camR[0], R1 = camR[1], R2 = camR[2];
    const float R3 = camR[3], R4 = camR[4], R5 = camR[5];
    const float R6 = camR[6], R7 = camR[7], R8 = camR[8];
    const float T0 = camT[0], T1 = camT[1], T2 = camT[2];

    // origin = -R^T T ;  dir = R^T dirs_cam   (Rt[i][j] = R[j][i])
    const float ox = -(R0 * T0 + R3 * T1 + R6 * T2);
    const float oy = -(R1 * T0 + R4 * T1 + R7 * T2);
    const float oz = -(R2 * T0 + R5 * T1 + R8 * T2);
    const float dx = R0 * dcx + R3 * dcy + R6;
    const float dy = R1 * dcx + R4 * dcy + R7;
    const float dz = R2 * dcx + R5 * dcy + R8;

    // Voxel-space affine map:  f = (o + d*depth)*SC + 127.5, depth = 2 + p*DSTEP
    //   f(p) = [ (o + 2d)*SC + 127.5 ]  +  p * [ d*DSTEP*SC ]
    const float SC = 127.5f / HALF;
    const float cx0 = fmaf(fmaf(dx, 2.0f, ox), SC, 127.5f);
    const float cy0 = fmaf(fmaf(dy, 2.0f, oy), SC, 127.5f);
    const float cz0 = fmaf(fmaf(dz, 2.0f, oz), SC, 127.5f);
    const float sx = dx * (DSTEP * SC);
    const float sy = dy * (DSTEP * SC);
    const float sz = dz * (DSTEP * SC);

    // Per-ray slab bounds on p (widened by 1; per-step test stays exact)
    float tlo = -1e30f, thi = 1e30f;
    axis_bounds(cx0, sx, tlo, thi);
    axis_bounds(cy0, sy, tlo, thi);
    axis_bounds(cz0, sz, tlo, thi);

    int plo, phi;
    if (tlo > thi) { plo = 0x7fffffff; phi = -1; }           // ray misses box
    else {
        plo = (int)floorf(fmaxf(tlo - 1.0f, 0.0f));
        phi = (int)ceilf (fminf(thi + 1.0f, 319.0f));
    }

    const int p0 = c * CSTEP;
    int ps = max(p0, plo);
    int pe = min(p0 + CSTEP - 1, phi);
    const int ps_l = (ps <= pe) ? ps : 0x7fffffff;
    const int pe_l = (ps <= pe) ? pe : -1;
    const int ws = __reduce_min_sync(0xffffffffu, ps_l);
    const int we = __reduce_max_sync(0xffffffffu, pe_l);

    float Tr  = 1.0f;
    float acc = 0.0f;

    if (ws <= we) {
        #pragma unroll 4
        for (int p = ws; p <= we; p++) {
            const float fp = (float)p;
            const float fx = fmaf(fp, sx, cx0);
            const float fy = fmaf(fp, sy, cy0);
            const float fz = fmaf(fp, sz, cz0);

            const bool inside = (fx >= 0.0f) & (fx <= 255.0f)
                              & (fy >= 0.0f) & (fy <= 255.0f)
                              & (fz >= 0.0f) & (fz <= 255.0f);
            if (inside) {
                const int x0 = (int)fx;          // fx >= 0 -> trunc == floor
                const int y0 = (int)fy;
                const int z0 = (int)fz;
                const float wx = fx - (float)x0;
                const float wy = fy - (float)y0;
                const float wz = fz - (float)z0;

                const int base = (z0 << 16) + (y0 << 8) + x0;
                const int xo = (x0 < 255) ? 1     : 0;
                const int yo = (y0 < 255) ? 256   : 0;
                const int zo = (z0 < 255) ? 65536 : 0;

                const float v000 = __ldg(vol + base);
                const float v001 = __ldg(vol + base + xo);
                const float v010 = __ldg(vol + base + yo);
                const float v011 = __ldg(vol + base + yo + xo);
                const float v100 = __ldg(vol + base + zo);
                const float v101 = __ldg(vol + base + zo + xo);
                const float v110 = __ldg(vol + base + zo + yo);
                const float v111 = __ldg(vol + base + zo + yo + xo);

                const float c00 = fmaf(wx, v001 - v000, v000);
                const float c01 = fmaf(wx, v011 - v010, v010);
                const float c10 = fmaf(wx, v101 - v100, v100);
                const float c11 = fmaf(wx, v111 - v110, v110);
                const float c0  = fmaf(wy, c01 - c00, c00);
                const float c1  = fmaf(wy, c11 - c10, c10);
                const float s   = fmaf(wz, c1 - c0, c0);

                // alpha = 0.1 exactly (constant density); 1-0.1+1e-10 -> 0.9f
                acc = fmaf(0.1f * Tr, s, acc);
                Tr *= 0.9f;
            }
            // outside: one_m = 1 + 1e-10 -> 1.0f: Tr unchanged
        }
    }

    const int pix = (h << 8) + w;
    g_cRGB[c * NPIX + pix] = acc;
    g_cT[c * NPIX + pix]   = Tr;
}

// ===========================================================================
// Kernel 2: combine chunks front-to-back, store gray, per-block partials;
// LAST block (self-resetting counter) does the deterministic final reduction.
// ===========================================================================
__global__ __launch_bounds__(256) void combine_k()
{
    const int t   = threadIdx.x;
    const int pix = (blockIdx.x << 8) + t;

    float T = 1.0f, G = 0.0f;
    #pragma unroll
    for (int c = 0; c < NC; c++) {
        G = fmaf(T, g_cRGB[c * NPIX + pix], G);
        T *= g_cT[c * NPIX + pix];
    }
    g_gray[pix] = G;

    __shared__ float ssum[256], ssq[256], smin[256], smax[256];
    ssum[t] = G; ssq[t] = G * G; smin[t] = G; smax[t] = G;
    for (int o = 128; o > 0; o >>= 1) {
        __syncthreads();
        if (t < o) {
            ssum[t] += ssum[t + o];
            ssq[t]  += ssq[t + o];
            smin[t]  = fminf(smin[t], smin[t + o]);
            smax[t]  = fmaxf(smax[t], smax[t + o]);
        }
    }

    __shared__ bool last;
    if (t == 0) {
        g_psum[blockIdx.x] = ssum[0];
        g_psq[blockIdx.x]  = ssq[0];
        g_pmin[blockIdx.x] = smin[0];
        g_pmax[blockIdx.x] = smax[0];
        __threadfence();
        last = (atomicInc(&g_cnt, 255u) == 255u);   // wraps to 0: graph-replay safe
    }
    __syncthreads();
    if (!last) return;

    __shared__ double dsum[256], dsq[256];
    __shared__ float  fmn[256], fmx[256];
    dsum[t] = (double)g_psum[t];
    dsq[t]  = (double)g_psq[t];
    fmn[t]  = g_pmin[t];
    fmx[t]  = g_pmax[t];
    for (int o = 128; o > 0; o >>= 1) {
        __syncthreads();
        if (t < o) {
            dsum[t] += dsum[t + o];
            dsq[t]  += dsq[t + o];
            fmn[t]   = fminf(fmn[t], fmn[t + o]);
            fmx[t]   = fmaxf(fmx[t], fmx[t + o]);
        }
    }
    if (t == 0) {
        const double N = (double)NPIX;
        const double sum = dsum[0], sq = dsq[0];
        const double mean = sum / N;
        double var = (sq - sum * sum / N) / (N - 1.0);
        if (var < 0.0) var = 0.0;
        const float meanf = (float)mean;
        const float s     = (float)sqrt(var) + 1e-8f;     // sigma(ddof=1) + EPS
        const float stdmn = (fmn[0] - meanf) / s;
        const float stdmx = (fmx[0] - meanf) / s;
        g_scal[0] = meanf;
        g_scal[1] = s;
        g_scal[2] = stdmn;
        g_scal[3] = stdmx - stdmn + 1e-8f;                // denom
    }
}

// ===========================================================================
// Kernel 3: normalize + transpose, both sides coalesced via 32x32 smem tile.
// ===========================================================================
__global__ __launch_bounds__(256) void norm_k(float* __restrict__ out)
{
    __shared__ float tile[32][33];
    const int tx = threadIdx.x;          // 0..31
    const int ty = threadIdx.y;          // 0..7
    const int wbase = blockIdx.x << 5;
    const int hbase = blockIdx.y << 5;

    #pragma unroll
    for (int j = 0; j < 32; j += 8) {
        const int h = hbase + ty + j;
        tile[ty + j][tx] = g_gray[(h << 8) + wbase + tx];   // coalesced (w contiguous)
    }
    __syncthreads();

    const float mean  = g_scal[0];
    const float s     = g_scal[1];
    const float stdmn = g_scal[2];
    const float denom = g_scal[3];

    #pragma unroll
    for (int j = 0; j < 32; j += 8) {
        const int w = wbase + ty + j;
        const float g = tile[tx][ty + j];
        const float stdv = (g - mean) / s;
        out[(w << 8) + hbase + tx] = (stdv - stdmn + 1e-8f) / denom;  // coalesced (h contiguous)
    }
}

extern "C" void kernel_launch(void* const* d_in, const int* in_sizes, int n_in,
                              void* d_out, int out_size)
{
    const float* vol  = (const float*)d_in[0];   // image3d (1,1,256,256,256)
    const float* camR = (const float*)d_in[1];   // (1,3,3)
    const float* camT = (const float*)d_in[2];   // (1,3)
    float* out = (float*)d_out;                  // (1,1,256,256)

    render_k<<<dim3(256, NC), 256>>>(vol, camR, camT);
    combine_k<<<256, 256>>>();
    norm_k<<<dim3(8, 8), dim3(32, 8)>>>(out);
}

// round 4
// speedup vs baseline: 1.9474x; 1.0578x over previous
#include <cuda_runtime.h>

#define FOV_TAN 0.57735026918962576451f   // tan(30 deg)
#define HALF    1.494140625f              // 255 * (3/256) * 0.5
#define NC      5                         // depth chunks
#define CSTEP   64                        // 320 / NC
#define NPIX    65536
#define DSTEP   (4.0f / 319.0f)           // linspace(2,6,320) step

// ---- scratch (static device arrays; no allocations allowed) ----
__device__ float g_cRGB[NC * NPIX];
__device__ float g_cT[NC * NPIX];
__device__ float g_gray[NPIX];
__device__ float g_psum[256], g_psq[256], g_pmin[256], g_pmax[256];
__device__ float g_scal[4];          // mean, sigma+eps, stdmin, denom
__device__ unsigned g_cnt = 0;       // self-resetting last-block counter

// Intersect fx(p) = c0 + s*p with [0, 255]; accumulate into [tlo, thi].
__device__ __forceinline__ void axis_bounds(float c0, float s, float& tlo, float& thi)
{
    if (s > 0.0f) {
        tlo = fmaxf(tlo, (0.0f   - c0) / s);
        thi = fminf(thi, (255.0f - c0) / s);
    } else if (s < 0.0f) {
        tlo = fmaxf(tlo, (255.0f - c0) / s);
        thi = fminf(thi, (0.0f   - c0) / s);
    } else if (c0 < 0.0f || c0 > 255.0f) {
        tlo = 1e30f; thi = -1e30f;
    }
}

// ===========================================================================
// Kernel 1: ray-march one depth chunk per block. block = one image row
// (256 w), grid = (256 h, NC chunks). Branchless body: unconditional clamped
// loads + select-masked compositing so ptxas can software-pipeline the loads
// across unrolled iterations (MLP >> 8).
// ===========================================================================
__global__ __launch_bounds__(256) void render_k(
    const float* __restrict__ vol,
    const float* __restrict__ camR,
    const float* __restrict__ camT)
{
    const int w = threadIdx.x;
    const int h = blockIdx.x;
    const int c = blockIdx.y;

    // linspace(-1, 1, 256)
    const float gx = fmaf((float)w, 2.0f / 255.0f, -1.0f);
    const float gy = fmaf((float)h, 2.0f / 255.0f, -1.0f);
    const float dcx = gx * FOV_TAN;
    const float dcy = gy * FOV_TAN;

    const float R0 = camR[0], R1 = camR[1], R2 = camR[2];
    const float R3 = camR[3], R4 = camR[4], R5 = camR[5];
    const float R6 = camR[6], R7 = camR[7], R8 = camR[8];
    const float T0 = camT[0], T1 = camT[1], T2 = camT[2];

    // origin = -R^T T ;  dir = R^T dirs_cam   (Rt[i][j] = R[j][i])
    const float ox = -(R0 * T0 + R3 * T1 + R6 * T2);
    const float oy = -(R1 * T0 + R4 * T1 + R7 * T2);
    const float oz = -(R2 * T0 + R5 * T1 + R8 * T2);
    const float dx = R0 * dcx + R3 * dcy + R6;
    const float dy = R1 * dcx + R4 * dcy + R7;
    const float dz = R2 * dcx + R5 * dcy + R8;

    // Voxel-space affine map:  f(p) = c0 + p*s   (depth = 2 + p*DSTEP)
    const float SC = 127.5f / HALF;
    const float cx0 = fmaf(fmaf(dx, 2.0f, ox), SC, 127.5f);
    const float cy0 = fmaf(fmaf(dy, 2.0f, oy), SC, 127.5f);
    const float cz0 = fmaf(fmaf(dz, 2.0f, oz), SC, 127.5f);
    const float sx = dx * (DSTEP * SC);
    const float sy = dy * (DSTEP * SC);
    const float sz = dz * (DSTEP * SC);

    // Per-ray slab bounds on p (widened by 1; per-step mask stays exact)
    float tlo = -1e30f, thi = 1e30f;
    axis_bounds(cx0, sx, tlo, thi);
    axis_bounds(cy0, sy, tlo, thi);
    axis_bounds(cz0, sz, tlo, thi);

    int plo, phi;
    if (tlo > thi) { plo = 0x7fffffff; phi = -1; }           // ray misses box
    else {
        plo = (int)floorf(fmaxf(tlo - 1.0f, 0.0f));
        phi = (int)ceilf (fminf(thi + 1.0f, 319.0f));
    }

    const int p0 = c * CSTEP;
    int ps = max(p0, plo);
    int pe = min(p0 + CSTEP - 1, phi);
    const int ps_l = (ps <= pe) ? ps : 0x7fffffff;
    const int pe_l = (ps <= pe) ? pe : -1;
    const int ws = __reduce_min_sync(0xffffffffu, ps_l);
    const int we = __reduce_max_sync(0xffffffffu, pe_l);

    float Tr  = 1.0f;
    float acc = 0.0f;

    if (ws <= we) {
        #pragma unroll 4
        for (int p = ws; p <= we; p++) {
            const float fp = (float)p;
            const float fx = fmaf(fp, sx, cx0);
            const float fy = fmaf(fp, sy, cy0);
            const float fz = fmaf(fp, sz, cz0);

            const bool inside = (fx >= 0.0f) & (fx <= 255.0f)
                              & (fy >= 0.0f) & (fy <= 255.0f)
                              & (fz >= 0.0f) & (fz <= 255.0f);

            // Clamp to [0,254]: at f==255 this yields w==1.0 which
            // interpolates to the boundary voxel exactly (±1 ulp).
            // Constant neighbor offsets -> one base addr + immediate LDGs.
            const int x0 = min(max((int)fx, 0), 254);
            const int y0 = min(max((int)fy, 0), 254);
            const int z0 = min(max((int)fz, 0), 254);
            const float wx = fx - (float)x0;
            const float wy = fy - (float)y0;
            const float wz = fz - (float)z0;

            const float* b = vol + ((z0 << 16) + (y0 << 8) + x0);
            const float v000 = __ldg(b);
            const float v001 = __ldg(b + 1);
            const float v010 = __ldg(b + 256);
            const float v011 = __ldg(b + 257);
            const float v100 = __ldg(b + 65536);
            const float v101 = __ldg(b + 65537);
            const float v110 = __ldg(b + 65792);
            const float v111 = __ldg(b + 65793);

            const float c00 = fmaf(wx, v001 - v000, v000);
            const float c01 = fmaf(wx, v011 - v010, v010);
            const float c10 = fmaf(wx, v101 - v100, v100);
            const float c11 = fmaf(wx, v111 - v110, v110);
            const float c0  = fmaf(wy, c01 - c00, c00);
            const float c1  = fmaf(wy, c11 - c10, c10);
            const float s   = fmaf(wz, c1 - c0, c0);

            // alpha = 0.1 exactly (constant density); masked outside.
            const float a  = inside ? 0.1f : 0.0f;   // weight select
            const float tm = inside ? 0.9f : 1.0f;   // transmittance select
            acc = fmaf(a * s, Tr, acc);              // a*s off the Tr chain
            Tr *= tm;
        }
    }

    const int pix = (h << 8) + w;
    g_cRGB[c * NPIX + pix] = acc;
    g_cT[c * NPIX + pix]   = Tr;
}

// ===========================================================================
// Kernel 2: combine chunks front-to-back, store gray, per-block partials;
// LAST block (self-resetting counter) does the deterministic final reduction.
// ===========================================================================
__global__ __launch_bounds__(256) void combine_k()
{
    const int t   = threadIdx.x;
    const int pix = (blockIdx.x << 8) + t;

    float T = 1.0f, G = 0.0f;
    #pragma unroll
    for (int c = 0; c < NC; c++) {
        G = fmaf(T, g_cRGB[c * NPIX + pix], G);
        T *= g_cT[c * NPIX + pix];
    }
    g_gray[pix] = G;

    __shared__ float ssum[256], ssq[256], smin[256], smax[256];
    ssum[t] = G; ssq[t] = G * G; smin[t] = G; smax[t] = G;
    for (int o = 128; o > 0; o >>= 1) {
        __syncthreads();
        if (t < o) {
            ssum[t] += ssum[t + o];
            ssq[t]  += ssq[t + o];
            smin[t]  = fminf(smin[t], smin[t + o]);
            smax[t]  = fmaxf(smax[t], smax[t + o]);
        }
    }

    __shared__ bool last;
    if (t == 0) {
        g_psum[blockIdx.x] = ssum[0];
        g_psq[blockIdx.x]  = ssq[0];
        g_pmin[blockIdx.x] = smin[0];
        g_pmax[blockIdx.x] = smax[0];
        __threadfence();
        last = (atomicInc(&g_cnt, 255u) == 255u);   // wraps to 0: graph-replay safe
    }
    __syncthreads();
    if (!last) return;

    __shared__ double dsum[256], dsq[256];
    __shared__ float  fmn[256], fmx[256];
    dsum[t] = (double)g_psum[t];
    dsq[t]  = (double)g_psq[t];
    fmn[t]  = g_pmin[t];
    fmx[t]  = g_pmax[t];
    for (int o = 128; o > 0; o >>= 1) {
        __syncthreads();
        if (t < o) {
            dsum[t] += dsum[t + o];
            dsq[t]  += dsq[t + o];
            fmn[t]   = fminf(fmn[t], fmn[t + o]);
            fmx[t]   = fmaxf(fmx[t], fmx[t + o]);
        }
    }
    if (t == 0) {
        const double N = (double)NPIX;
        const double sum = dsum[0], sq = dsq[0];
        const double mean = sum / N;
        double var = (sq - sum * sum / N) / (N - 1.0);
        if (var < 0.0) var = 0.0;
        const float meanf = (float)mean;
        const float s     = (float)sqrt(var) + 1e-8f;     // sigma(ddof=1) + EPS
        const float stdmn = (fmn[0] - meanf) / s;
        const float stdmx = (fmx[0] - meanf) / s;
        g_scal[0] = meanf;
        g_scal[1] = s;
        g_scal[2] = stdmn;
        g_scal[3] = stdmx - stdmn + 1e-8f;                // denom
    }
}

// ===========================================================================
// Kernel 3: normalize + transpose, both sides coalesced via 32x32 smem tile.
// ===========================================================================
__global__ __launch_bounds__(256) void norm_k(float* __restrict__ out)
{
    __shared__ float tile[32][33];
    const int tx = threadIdx.x;          // 0..31
    const int ty = threadIdx.y;          // 0..7
    const int wbase = blockIdx.x << 5;
    const int hbase = blockIdx.y << 5;

    #pragma unroll
    for (int j = 0; j < 32; j += 8) {
        const int h = hbase + ty + j;
        tile[ty + j][tx] = g_gray[(h << 8) + wbase + tx];   // coalesced (w contiguous)
    }
    __syncthreads();

    const float mean  = g_scal[0];
    const float s     = g_scal[1];
    const float stdmn = g_scal[2];
    const float denom = g_scal[3];

    #pragma unroll
    for (int j = 0; j < 32; j += 8) {
        const int w = wbase + ty + j;
        const float g = tile[tx][ty + j];
        const float stdv = (g - mean) / s;
        out[(w << 8) + hbase + tx] = (stdv - stdmn + 1e-8f) / denom;  // coalesced (h contiguous)
    }
}

extern "C" void kernel_launch(void* const* d_in, const int* in_sizes, int n_in,
                              void* d_out, int out_size)
{
    const float* vol  = (const float*)d_in[0];   // image3d (1,1,256,256,256)
    const float* camR = (const float*)d_in[1];   // (1,3,3)
    const float* camT = (const float*)d_in[2];   // (1,3)
    float* out = (float*)d_out;                  // (1,1,256,256)

    render_k<<<dim3(256, NC), 256>>>(vol, camR, camT);
    combine_k<<<256, 256>>>();
    norm_k<<<dim3(8, 8), dim3(32, 8)>>>(out);
}

// round 5
// speedup vs baseline: 2.1253x; 1.0914x over previous
#include <cuda_runtime.h>

#define FOV_TAN 0.57735026918962576451f   // tan(30 deg)
#define HALF    1.494140625f              // 255 * (3/256) * 0.5
#define NC      5                         // depth chunks
#define CSTEP   64                        // 320 / NC
#define NPIX    65536
#define DSTEP   (4.0f / 319.0f)           // linspace(2,6,320) step

// ---- scratch (static device arrays; no allocations allowed) ----
__device__ float g_cRGB[NC * NPIX];
__device__ float g_cT[NC * NPIX];
__device__ float g_gray[NPIX];
__device__ float g_psum[256], g_psq[256], g_pmin[256], g_pmax[256];
__device__ float g_scal[4];          // mean, sigma+eps, stdmin, denom
__device__ unsigned g_cnt = 0;       // self-resetting last-block counter

// Intersect f(p) = c0 + s*p with [0, 255]; accumulate into [tlo, thi].
__device__ __forceinline__ void axis_bounds(float c0, float s, float& tlo, float& thi)
{
    if (s > 0.0f) {
        tlo = fmaxf(tlo, (0.0f   - c0) / s);
        thi = fminf(thi, (255.0f - c0) / s);
    } else if (s < 0.0f) {
        tlo = fmaxf(tlo, (255.0f - c0) / s);
        thi = fminf(thi, (0.0f   - c0) / s);
    } else if (c0 < 0.0f || c0 > 255.0f) {
        tlo = 1e30f; thi = -1e30f;
    }
}

// One sample: coords -> clamped base + weights + inside mask (no loads here).
__device__ __forceinline__ void sample_setup(
    float fp, float sx, float sy, float sz,
    float cx0, float cy0, float cz0,
    const float* __restrict__ vol,
    const float*& b, float& wx, float& wy, float& wz, bool& inside)
{
    const float fx = fmaf(fp, sx, cx0);
    const float fy = fmaf(fp, sy, cy0);
    const float fz = fmaf(fp, sz, cz0);
    inside = (fx >= 0.0f) & (fx <= 255.0f)
           & (fy >= 0.0f) & (fy <= 255.0f)
           & (fz >= 0.0f) & (fz <= 255.0f);
    const int x0 = min(max((int)fx, 0), 254);
    const int y0 = min(max((int)fy, 0), 254);
    const int z0 = min(max((int)fz, 0), 254);
    wx = fx - (float)x0;
    wy = fy - (float)y0;
    wz = fz - (float)z0;
    b = vol + ((z0 << 16) + (y0 << 8) + x0);
}

__device__ __forceinline__ float tri_tree(
    const float v[8], float wx, float wy, float wz)
{
    const float c00 = fmaf(wx, v[1] - v[0], v[0]);
    const float c01 = fmaf(wx, v[3] - v[2], v[2]);
    const float c10 = fmaf(wx, v[5] - v[4], v[4]);
    const float c11 = fmaf(wx, v[7] - v[6], v[6]);
    const float c0  = fmaf(wy, c01 - c00, c00);
    const float c1  = fmaf(wy, c11 - c10, c10);
    return fmaf(wz, c1 - c0, c0);
}

#define LOAD8(v, b)                 \
    v[0] = __ldg(b);                \
    v[1] = __ldg(b + 1);            \
    v[2] = __ldg(b + 256);          \
    v[3] = __ldg(b + 257);          \
    v[4] = __ldg(b + 65536);        \
    v[5] = __ldg(b + 65537);        \
    v[6] = __ldg(b + 65792);        \
    v[7] = __ldg(b + 65793);

// ===========================================================================
// Kernel 1: ray-march one depth chunk per block. block = one image row
// (256 w), grid = (256 h, NC chunks). Explicit 2-step software pipeline:
// all 16 loads issued before any interpolation -> MLP ~16/warp.
// ===========================================================================
__global__ __launch_bounds__(256, 3) void render_k(
    const float* __restrict__ vol,
    const float* __restrict__ camR,
    const float* __restrict__ camT)
{
    const int w = threadIdx.x;
    const int h = blockIdx.x;
    const int c = blockIdx.y;

    const float gx = fmaf((float)w, 2.0f / 255.0f, -1.0f);
    const float gy = fmaf((float)h, 2.0f / 255.0f, -1.0f);
    const float dcx = gx * FOV_TAN;
    const float dcy = gy * FOV_TAN;

    const float R0 = camR[0], R1 = camR[1], R2 = camR[2];
    const float R3 = camR[3], R4 = camR[4], R5 = camR[5];
    const float R6 = camR[6], R7 = camR[7], R8 = camR[8];
    const float T0 = camT[0], T1 = camT[1], T2 = camT[2];

    const float ox = -(R0 * T0 + R3 * T1 + R6 * T2);
    const float oy = -(R1 * T0 + R4 * T1 + R7 * T2);
    const float oz = -(R2 * T0 + R5 * T1 + R8 * T2);
    const float dx = R0 * dcx + R3 * dcy + R6;
    const float dy = R1 * dcx + R4 * dcy + R7;
    const float dz = R2 * dcx + R5 * dcy + R8;

    // Voxel-space affine map:  f(p) = c0 + p*s   (depth = 2 + p*DSTEP)
    const float SC = 127.5f / HALF;
    const float cx0 = fmaf(fmaf(dx, 2.0f, ox), SC, 127.5f);
    const float cy0 = fmaf(fmaf(dy, 2.0f, oy), SC, 127.5f);
    const float cz0 = fmaf(fmaf(dz, 2.0f, oz), SC, 127.5f);
    const float sx = dx * (DSTEP * SC);
    const float sy = dy * (DSTEP * SC);
    const float sz = dz * (DSTEP * SC);

    // Per-ray slab bounds on p (widened by 1; per-step mask stays exact)
    float tlo = -1e30f, thi = 1e30f;
    axis_bounds(cx0, sx, tlo, thi);
    axis_bounds(cy0, sy, tlo, thi);
    axis_bounds(cz0, sz, tlo, thi);

    int plo, phi;
    if (tlo > thi) { plo = 0x7fffffff; phi = -1; }
    else {
        plo = (int)floorf(fmaxf(tlo - 1.0f, 0.0f));
        phi = (int)ceilf (fminf(thi + 1.0f, 319.0f));
    }

    const int p0 = c * CSTEP;
    int ps = max(p0, plo);
    int pe = min(p0 + CSTEP - 1, phi);
    const int ps_l = (ps <= pe) ? ps : 0x7fffffff;
    const int pe_l = (ps <= pe) ? pe : -1;
    const int ws = __reduce_min_sync(0xffffffffu, ps_l);
    const int we = __reduce_max_sync(0xffffffffu, pe_l);

    float Tr  = 1.0f;
    float acc = 0.0f;

    int p = ws;
    // ---- pipelined pairs: 16 loads in flight before any interpolation ----
    for (; p + 1 <= we; p += 2) {
        const float* b0; float wx0, wy0, wz0; bool in0;
        const float* b1; float wx1, wy1, wz1; bool in1;
        sample_setup((float)p,       sx, sy, sz, cx0, cy0, cz0, vol, b0, wx0, wy0, wz0, in0);
        sample_setup((float)(p + 1), sx, sy, sz, cx0, cy0, cz0, vol, b1, wx1, wy1, wz1, in1);

        float va[8], vb[8];
        LOAD8(va, b0)
        LOAD8(vb, b1)

        const float s0 = tri_tree(va, wx0, wy0, wz0);
        const float s1 = tri_tree(vb, wx1, wy1, wz1);

        // alpha = 0.1 exactly (constant density); masked outside.
        acc = fmaf((in0 ? 0.1f : 0.0f) * s0, Tr, acc);
        Tr *= in0 ? 0.9f : 1.0f;
        acc = fmaf((in1 ? 0.1f : 0.0f) * s1, Tr, acc);
        Tr *= in1 ? 0.9f : 1.0f;
    }
    // ---- tail ----
    if (p <= we) {
        const float* b0; float wx0, wy0, wz0; bool in0;
        sample_setup((float)p, sx, sy, sz, cx0, cy0, cz0, vol, b0, wx0, wy0, wz0, in0);
        float va[8];
        LOAD8(va, b0)
        const float s0 = tri_tree(va, wx0, wy0, wz0);
        acc = fmaf((in0 ? 0.1f : 0.0f) * s0, Tr, acc);
        Tr *= in0 ? 0.9f : 1.0f;
    }

    const int pix = (h << 8) + w;
    g_cRGB[c * NPIX + pix] = acc;
    g_cT[c * NPIX + pix]   = Tr;
}

// ===========================================================================
// Kernel 2: combine chunks front-to-back, store gray, per-block partials;
// LAST block (self-resetting counter) does the deterministic final reduction.
// ===========================================================================
__global__ __launch_bounds__(256) void combine_k()
{
    const int t   = threadIdx.x;
    const int pix = (blockIdx.x << 8) + t;

    float T = 1.0f, G = 0.0f;
    #pragma unroll
    for (int c = 0; c < NC; c++) {
        G = fmaf(T, g_cRGB[c * NPIX + pix], G);
        T *= g_cT[c * NPIX + pix];
    }
    g_gray[pix] = G;

    __shared__ float ssum[256], ssq[256], smin[256], smax[256];
    ssum[t] = G; ssq[t] = G * G; smin[t] = G; smax[t] = G;
    for (int o = 128; o > 0; o >>= 1) {
        __syncthreads();
        if (t < o) {
            ssum[t] += ssum[t + o];
            ssq[t]  += ssq[t + o];
            smin[t]  = fminf(smin[t], smin[t + o]);
            smax[t]  = fmaxf(smax[t], smax[t + o]);
        }
    }

    __shared__ bool last;
    if (t == 0) {
        g_psum[blockIdx.x] = ssum[0];
        g_psq[blockIdx.x]  = ssq[0];
        g_pmin[blockIdx.x] = smin[0];
        g_pmax[blockIdx.x] = smax[0];
        __threadfence();
        last = (atomicInc(&g_cnt, 255u) == 255u);   // wraps to 0: graph-replay safe
    }
    __syncthreads();
    if (!last) return;

    __shared__ double dsum[256], dsq[256];
    __shared__ float  fmn[256], fmx[256];
    dsum[t] = (double)g_psum[t];
    dsq[t]  = (double)g_psq[t];
    fmn[t]  = g_pmin[t];
    fmx[t]  = g_pmax[t];
    for (int o = 128; o > 0; o >>= 1) {
        __syncthreads();
        if (t < o) {
            dsum[t] += dsum[t + o];
            dsq[t]  += dsq[t + o];
            fmn[t]   = fminf(fmn[t], fmn[t + o]);
            fmx[t]   = fmaxf(fmx[t], fmx[t + o]);
        }
    }
    if (t == 0) {
        const double N = (double)NPIX;
        const double sum = dsum[0], sq = dsq[0];
        const double mean = sum / N;
        double var = (sq - sum * sum / N) / (N - 1.0);
        if (var < 0.0) var = 0.0;
        const float meanf = (float)mean;
        const float s     = (float)sqrt(var) + 1e-8f;     // sigma(ddof=1) + EPS
        const float stdmn = (fmn[0] - meanf) / s;
        const float stdmx = (fmx[0] - meanf) / s;
        g_scal[0] = meanf;
        g_scal[1] = s;
        g_scal[2] = stdmn;
        g_scal[3] = stdmx - stdmn + 1e-8f;                // denom
    }
}

// ===========================================================================
// Kernel 3: normalize + transpose, both sides coalesced via 32x32 smem tile.
// ===========================================================================
__global__ __launch_bounds__(256) void norm_k(float* __restrict__ out)
{
    __shared__ float tile[32][33];
    const int tx = threadIdx.x;          // 0..31
    const int ty = threadIdx.y;          // 0..7
    const int wbase = blockIdx.x << 5;
    const int hbase = blockIdx.y << 5;

    #pragma unroll
    for (int j = 0; j < 32; j += 8) {
        const int h = hbase + ty + j;
        tile[ty + j][tx] = g_gray[(h << 8) + wbase + tx];   // coalesced (w contiguous)
    }
    __syncthreads();

    const float mean  = g_scal[0];
    const float s     = g_scal[1];
    const float stdmn = g_scal[2];
    const float denom = g_scal[3];

    #pragma unroll
    for (int j = 0; j < 32; j += 8) {
        const int w = wbase + ty + j;
        const float g = tile[tx][ty + j];
        const float stdv = (g - mean) / s;
        out[(w << 8) + hbase + tx] = (stdv - stdmn + 1e-8f) / denom;  // coalesced (h contiguous)
    }
}

extern "C" void kernel_launch(void* const* d_in, const int* in_sizes, int n_in,
                              void* d_out, int out_size)
{
    const float* vol  = (const float*)d_in[0];   // image3d (1,1,256,256,256)
    const float* camR = (const float*)d_in[1];   // (1,3,3)
    const float* camT = (const float*)d_in[2];   // (1,3)
    float* out = (float*)d_out;                  // (1,1,256,256)

    render_k<<<dim3(256, NC), 256>>>(vol, camR, camT);
    combine_k<<<256, 256>>>();
    norm_k<<<dim3(8, 8), dim3(32, 8)>>>(out);
}

// round 7
// speedup vs baseline: 2.2148x; 1.0421x over previous
#include <cuda_runtime.h>

#define FOV_TAN 0.57735026918962576451f   // tan(30 deg)
#define HALF    1.494140625f              // 255 * (3/256) * 0.5
#define NC      5                         // depth chunks
#define CSTEP   64                        // 320 / NC
#define NPIX    65536
#define DSTEP   (4.0f / 319.0f)           // linspace(2,6,320) step

// ---- scratch (static device arrays; no allocations allowed) ----
__device__ float g_cRGB[NC * NPIX];
__device__ float g_cT[NC * NPIX];
__device__ float g_gray[NPIX];
__device__ float g_psum[256], g_psq[256], g_pmin[256], g_pmax[256];
__device__ float g_scal[4];          // mean, sigma+eps, stdmin, denom
__device__ unsigned g_cnt = 0;       // self-resetting last-block counter

// Intersect f(p) = c0 + s*p with [0, 255]; accumulate into [tlo, thi].
__device__ __forceinline__ void axis_bounds(float c0, float s, float& tlo, float& thi)
{
    if (s > 0.0f) {
        tlo = fmaxf(tlo, (0.0f   - c0) / s);
        thi = fminf(thi, (255.0f - c0) / s);
    } else if (s < 0.0f) {
        tlo = fmaxf(tlo, (255.0f - c0) / s);
        thi = fminf(thi, (0.0f   - c0) / s);
    } else if (c0 < 0.0f || c0 > 255.0f) {
        tlo = 1e30f; thi = -1e30f;
    }
}

// One sample: coords -> clamped base + weights + inside mask (no loads).
__device__ __forceinline__ void sample_setup(
    float fp, float sx, float sy, float sz,
    float cx0, float cy0, float cz0,
    const float* __restrict__ vol,
    const float*& b, float& wx, float& wy, float& wz, bool& inside)
{
    const float fx = fmaf(fp, sx, cx0);
    const float fy = fmaf(fp, sy, cy0);
    const float fz = fmaf(fp, sz, cz0);
    inside = (fx >= 0.0f) & (fx <= 255.0f)
           & (fy >= 0.0f) & (fy <= 255.0f)
           & (fz >= 0.0f) & (fz <= 255.0f);
    // float clamp to [0,254] then single F2I (trunc == floor for >=0)
    const float fxc = fminf(fmaxf(fx, 0.0f), 254.0f);
    const float fyc = fminf(fmaxf(fy, 0.0f), 254.0f);
    const float fzc = fminf(fmaxf(fz, 0.0f), 254.0f);
    const int x0 = (int)fxc;
    const int y0 = (int)fyc;
    const int z0 = (int)fzc;
    wx = fx - (float)x0;
    wy = fy - (float)y0;
    wz = fz - (float)z0;
    b = vol + ((z0 << 16) + (y0 << 8) + x0);
}

__device__ __forceinline__ float tri_tree(
    const float v[8], float wx, float wy, float wz)
{
    const float c00 = fmaf(wx, v[1] - v[0], v[0]);
    const float c01 = fmaf(wx, v[3] - v[2], v[2]);
    const float c10 = fmaf(wx, v[5] - v[4], v[4]);
    const float c11 = fmaf(wx, v[7] - v[6], v[6]);
    const float c0  = fmaf(wy, c01 - c00, c00);
    const float c1  = fmaf(wy, c11 - c10, c10);
    return fmaf(wz, c1 - c0, c0);
}

#define LOAD8(v, b)                 \
    v[0] = __ldg(b);                \
    v[1] = __ldg(b + 1);            \
    v[2] = __ldg(b + 256);          \
    v[3] = __ldg(b + 257);          \
    v[4] = __ldg(b + 65536);        \
    v[5] = __ldg(b + 65537);        \
    v[6] = __ldg(b + 65792);        \
    v[7] = __ldg(b + 65793);

// ===========================================================================
// Kernel 1: ray-march one depth chunk per block. block = one image row
// (256 w), grid = (256 h, NC chunks). Explicit 4-step software pipeline:
// all 32 loads issued before any interpolation -> MLP ~32/warp.
// NOTE: the `if (ws <= we)` guard is LOAD-BEARING — when a whole warp has
// no samples, ws=INT_MAX and the loop condition would signed-overflow.
// ===========================================================================
__global__ __launch_bounds__(256, 2) void render_k(
    const float* __restrict__ vol,
    const float* __restrict__ camR,
    const float* __restrict__ camT)
{
    const int w = threadIdx.x;
    const int h = blockIdx.x;
    const int c = blockIdx.y;

    const float gx = fmaf((float)w, 2.0f / 255.0f, -1.0f);
    const float gy = fmaf((float)h, 2.0f / 255.0f, -1.0f);
    const float dcx = gx * FOV_TAN;
    const float dcy = gy * FOV_TAN;

    const float R0 = camR[0], R1 = camR[1], R2 = camR[2];
    const float R3 = camR[3], R4 = camR[4], R5 = camR[5];
    const float R6 = camR[6], R7 = camR[7], R8 = camR[8];
    const float T0 = camT[0], T1 = camT[1], T2 = camT[2];

    const float ox = -(R0 * T0 + R3 * T1 + R6 * T2);
    const float oy = -(R1 * T0 + R4 * T1 + R7 * T2);
    const float oz = -(R2 * T0 + R5 * T1 + R8 * T2);
    const float dx = R0 * dcx + R3 * dcy + R6;
    const float dy = R1 * dcx + R4 * dcy + R7;
    const float dz = R2 * dcx + R5 * dcy + R8;

    // Voxel-space affine map:  f(p) = c0 + p*s   (depth = 2 + p*DSTEP)
    const float SC = 127.5f / HALF;
    const float cx0 = fmaf(fmaf(dx, 2.0f, ox), SC, 127.5f);
    const float cy0 = fmaf(fmaf(dy, 2.0f, oy), SC, 127.5f);
    const float cz0 = fmaf(fmaf(dz, 2.0f, oz), SC, 127.5f);
    const float sx = dx * (DSTEP * SC);
    const float sy = dy * (DSTEP * SC);
    const float sz = dz * (DSTEP * SC);

    // Per-ray slab bounds on p (widened by 1; per-step mask stays exact)
    float tlo = -1e30f, thi = 1e30f;
    axis_bounds(cx0, sx, tlo, thi);
    axis_bounds(cy0, sy, tlo, thi);
    axis_bounds(cz0, sz, tlo, thi);

    int plo, phi;
    if (tlo > thi) { plo = 0x7fffffff; phi = -1; }
    else {
        plo = (int)floorf(fmaxf(tlo - 1.0f, 0.0f));
        phi = (int)ceilf (fminf(thi + 1.0f, 319.0f));
    }

    const int p0 = c * CSTEP;
    int ps = max(p0, plo);
    int pe = min(p0 + CSTEP - 1, phi);
    const int ps_l = (ps <= pe) ? ps : 0x7fffffff;
    const int pe_l = (ps <= pe) ? pe : -1;
    const int ws = __reduce_min_sync(0xffffffffu, ps_l);
    const int we = __reduce_max_sync(0xffffffffu, pe_l);

    float Tr  = 1.0f;
    float acc = 0.0f;

    if (ws <= we) {                       // guard: ws,we in [0,319] inside
        int p = ws;
        // ---- 4-step pipeline: 32 loads in flight before interpolation ----
        for (; p + 3 <= we; p += 4) {
            const float* b0; float wx0, wy0, wz0; bool in0;
            const float* b1; float wx1, wy1, wz1; bool in1;
            const float* b2; float wx2, wy2, wz2; bool in2;
            const float* b3; float wx3, wy3, wz3; bool in3;
            sample_setup((float)p,       sx, sy, sz, cx0, cy0, cz0, vol, b0, wx0, wy0, wz0, in0);
            sample_setup((float)(p + 1), sx, sy, sz, cx0, cy0, cz0, vol, b1, wx1, wy1, wz1, in1);
            sample_setup((float)(p + 2), sx, sy, sz, cx0, cy0, cz0, vol, b2, wx2, wy2, wz2, in2);
            sample_setup((float)(p + 3), sx, sy, sz, cx0, cy0, cz0, vol, b3, wx3, wy3, wz3, in3);

            float va[8], vb[8], vc[8], vd[8];
            LOAD8(va, b0)
            LOAD8(vb, b1)
            LOAD8(vc, b2)
            LOAD8(vd, b3)

            const float s0 = tri_tree(va, wx0, wy0, wz0);
            const float s1 = tri_tree(vb, wx1, wy1, wz1);
            const float s2 = tri_tree(vc, wx2, wy2, wz2);
            const float s3 = tri_tree(vd, wx3, wy3, wz3);

            // alpha = 0.1 exactly (constant density); masked outside.
            acc = fmaf((in0 ? 0.1f : 0.0f) * s0, Tr, acc);
            Tr *= in0 ? 0.9f : 1.0f;
            acc = fmaf((in1 ? 0.1f : 0.0f) * s1, Tr, acc);
            Tr *= in1 ? 0.9f : 1.0f;
            acc = fmaf((in2 ? 0.1f : 0.0f) * s2, Tr, acc);
            Tr *= in2 ? 0.9f : 1.0f;
            acc = fmaf((in3 ? 0.1f : 0.0f) * s3, Tr, acc);
            Tr *= in3 ? 0.9f : 1.0f;
        }
        // ---- tail (0..3 steps) ----
        for (; p <= we; p++) {
            const float* b0; float wx0, wy0, wz0; bool in0;
            sample_setup((float)p, sx, sy, sz, cx0, cy0, cz0, vol, b0, wx0, wy0, wz0, in0);
            float va[8];
            LOAD8(va, b0)
            const float s0 = tri_tree(va, wx0, wy0, wz0);
            acc = fmaf((in0 ? 0.1f : 0.0f) * s0, Tr, acc);
            Tr *= in0 ? 0.9f : 1.0f;
        }
    }

    const int pix = (h << 8) + w;
    g_cRGB[c * NPIX + pix] = acc;
    g_cT[c * NPIX + pix]   = Tr;
}

// ===========================================================================
// Kernel 2: combine chunks front-to-back, store gray, per-block partials;
// LAST block (self-resetting counter) does the deterministic final reduction.
// ===========================================================================
__global__ __launch_bounds__(256) void combine_k()
{
    const int t   = threadIdx.x;
    const int pix = (blockIdx.x << 8) + t;

    float T = 1.0f, G = 0.0f;
    #pragma unroll
    for (int c = 0; c < NC; c++) {
        G = fmaf(T, g_cRGB[c * NPIX + pix], G);
        T *= g_cT[c * NPIX + pix];
    }
    g_gray[pix] = G;

    __shared__ float ssum[256], ssq[256], smin[256], smax[256];
    ssum[t] = G; ssq[t] = G * G; smin[t] = G; smax[t] = G;
    for (int o = 128; o > 0; o >>= 1) {
        __syncthreads();
        if (t < o) {
            ssum[t] += ssum[t + o];
            ssq[t]  += ssq[t + o];
            smin[t]  = fminf(smin[t], smin[t + o]);
            smax[t]  = fmaxf(smax[t], smax[t + o]);
        }
    }

    __shared__ bool last;
    if (t == 0) {
        g_psum[blockIdx.x] = ssum[0];
        g_psq[blockIdx.x]  = ssq[0];
        g_pmin[blockIdx.x] = smin[0];
        g_pmax[blockIdx.x] = smax[0];
        __threadfence();
        last = (atomicInc(&g_cnt, 255u) == 255u);   // wraps to 0: graph-replay safe
    }
    __syncthreads();
    if (!last) return;

    __shared__ double dsum[256], dsq[256];
    __shared__ float  fmn[256], fmx[256];
    dsum[t] = (double)g_psum[t];
    dsq[t]  = (double)g_psq[t];
    fmn[t]  = g_pmin[t];
    fmx[t]  = g_pmax[t];
    for (int o = 128; o > 0; o >>= 1) {
        __syncthreads();
        if (t < o) {
            dsum[t] += dsum[t + o];
            dsq[t]  += dsq[t + o];
            fmn[t]   = fminf(fmn[t], fmn[t + o]);
            fmx[t]   = fmaxf(fmx[t], fmx[t + o]);
        }
    }
    if (t == 0) {
        const double N = (double)NPIX;
        const double sum = dsum[0], sq = dsq[0];
        const double mean = sum / N;
        double var = (sq - sum * sum / N) / (N - 1.0);
        if (var < 0.0) var = 0.0;
        const float meanf = (float)mean;
        const float s     = (float)sqrt(var) + 1e-8f;     // sigma(ddof=1) + EPS
        const float stdmn = (fmn[0] - meanf) / s;
        const float stdmx = (fmx[0] - meanf) / s;
        g_scal[0] = meanf;
        g_scal[1] = s;
        g_scal[2] = stdmn;
        g_scal[3] = stdmx - stdmn + 1e-8f;                // denom
    }
}

// ===========================================================================
// Kernel 3: normalize + transpose, both sides coalesced via 32x32 smem tile.
// ===========================================================================
__global__ __launch_bounds__(256) void norm_k(float* __restrict__ out)
{
    __shared__ float tile[32][33];
    const int tx = threadIdx.x;          // 0..31
    const int ty = threadIdx.y;          // 0..7
    const int wbase = blockIdx.x << 5;
    const int hbase = blockIdx.y << 5;

    #pragma unroll
    for (int j = 0; j < 32; j += 8) {
        const int h = hbase + ty + j;
        tile[ty + j][tx] = g_gray[(h << 8) + wbase + tx];   // coalesced (w contiguous)
    }
    __syncthreads();

    const float mean  = g_scal[0];
    const float s     = g_scal[1];
    const float stdmn = g_scal[2];
    const float denom = g_scal[3];

    #pragma unroll
    for (int j = 0; j < 32; j += 8) {
        const int w = wbase + ty + j;
        const float g = tile[tx][ty + j];
        const float stdv = (g - mean) / s;
        out[(w << 8) + hbase + tx] = (stdv - stdmn + 1e-8f) / denom;  // coalesced (h contiguous)
    }
}

extern "C" void kernel_launch(void* const* d_in, const int* in_sizes, int n_in,
                              void* d_out, int out_size)
{
    const float* vol  = (const float*)d_in[0];   // image3d (1,1,256,256,256)
    const float* camR = (const float*)d_in[1];   // (1,3,3)
    const float* camT = (const float*)d_in[2];   // (1,3)
    float* out = (float*)d_out;                  // (1,1,256,256)

    render_k<<<dim3(256, NC), 256>>>(vol, camR, camT);
    combine_k<<<256, 256>>>();
    norm_k<<<dim3(8, 8), dim3(32, 8)>>>(out);
}